// round 1
// baseline (speedup 1.0000x reference)
#include <cuda_runtime.h>
#include <cstdint>

#define BB 8
#define HH 64
#define WW 64
#define CC 512
#define NTOK (BB*HH*WW)        /* 32768 tokens */
#define E4D 2048
#define NHEADS 16
#define HD 32

// ---------------- scratch (device globals; no allocations allowed) ----------
__device__ float g_n1 [(size_t)NTOK * CC];        // 64 MB  (reused for ln2 out)
__device__ float g_qkv[(size_t)NTOK * 3 * CC];    // 192 MB
__device__ float g_att[(size_t)NTOK * CC];        // 64 MB
__device__ float g_msa[(size_t)NTOK * CC];        // 64 MB
__device__ float g_act[(size_t)NTOK * E4D];       // 256 MB

// ---------------- LayerNorm: one row (512) per block, 256 threads -----------
__global__ void ln_kernel(const float* __restrict__ in,
                          const float* __restrict__ g,
                          const float* __restrict__ b,
                          float* __restrict__ out) {
    int row = blockIdx.x;
    int tid = threadIdx.x;             // 256 threads, 2 floats each
    const float2* xr = (const float2*)(in + (size_t)row * CC);
    float2 v = xr[tid];
    float s  = v.x + v.y;
    float sq = v.x * v.x + v.y * v.y;
    #pragma unroll
    for (int o = 16; o; o >>= 1) {
        s  += __shfl_xor_sync(0xffffffffu, s,  o);
        sq += __shfl_xor_sync(0xffffffffu, sq, o);
    }
    __shared__ float ss[8], sqq[8];
    int w = tid >> 5, l = tid & 31;
    if (!l) { ss[w] = s; sqq[w] = sq; }
    __syncthreads();
    s = 0.f; sq = 0.f;
    #pragma unroll
    for (int i = 0; i < 8; i++) { s += ss[i]; sq += sqq[i]; }
    float mean = s * (1.f / CC);
    float var  = sq * (1.f / CC) - mean * mean;
    float rstd = rsqrtf(var + 1e-5f);
    float2 gg = ((const float2*)g)[tid];
    float2 bb = ((const float2*)b)[tid];
    float2 o;
    o.x = (v.x - mean) * rstd * gg.x + bb.x;
    o.y = (v.y - mean) * rstd * gg.y + bb.y;
    ((float2*)(out + (size_t)row * CC))[tid] = o;
}

// ---------------- TF32 helper ------------------------------------------------
__device__ __forceinline__ float f2tf(float x) {
    uint32_t r;
    asm("cvt.rna.tf32.f32 %0, %1;" : "=r"(r) : "f"(x));
    return __uint_as_float(r);
}

// ---------------- generic TF32 GEMM: out[N,M] = A[N,K] @ W[K,M] + epilogue ---
// EPI: 0 = +bias ; 1 = +bias + res[row,col] ; 2 = +bias then exact GELU
// block tile 128x128, k-tile 32, 8 warps (warp tile 64x32), mma m16n8k8 tf32
template<int EPI>
__global__ __launch_bounds__(256)
void gemm_tf32(const float* __restrict__ A, const float* __restrict__ W,
               const float* __restrict__ bias, const float* __restrict__ res,
               float* __restrict__ out, int K, int M) {
    __shared__ float As[128 * 36];   // stride 36: conflict-free frag reads
    __shared__ float Bs[32 * 136];   // stride 136 (mod 32 == 8): conflict-free

    int tid  = threadIdx.x;
    int lane = tid & 31;
    int warp = tid >> 5;
    int wm = warp & 1;               // 2 warps along M (2*64 = 128)
    int wn = warp >> 1;              // 4 warps along N (4*32 = 128)
    size_t rowBase = (size_t)blockIdx.y * 128;
    int    colBase = blockIdx.x * 128;

    float c[4][4][4];
    #pragma unroll
    for (int i = 0; i < 4; i++)
        #pragma unroll
        for (int j = 0; j < 4; j++)
            #pragma unroll
            for (int k = 0; k < 4; k++) c[i][j][k] = 0.f;

    for (int kt = 0; kt < K; kt += 32) {
        // load A tile 128x32 (row-major, K contiguous)
        #pragma unroll
        for (int i = 0; i < 4; i++) {
            int fi = tid + i * 256;
            int r  = fi >> 3;
            int c4 = (fi & 7) << 2;
            float4 v = *(const float4*)(A + (rowBase + r) * K + kt + c4);
            float* d = &As[r * 36 + c4];
            d[0] = f2tf(v.x); d[1] = f2tf(v.y); d[2] = f2tf(v.z); d[3] = f2tf(v.w);
        }
        // load B tile 32x128 (row-major, M contiguous)
        #pragma unroll
        for (int i = 0; i < 4; i++) {
            int fi = tid + i * 256;
            int r  = fi >> 5;
            int c4 = (fi & 31) << 2;
            float4 v = *(const float4*)(W + (size_t)(kt + r) * M + colBase + c4);
            float* d = &Bs[r * 136 + c4];
            d[0] = f2tf(v.x); d[1] = f2tf(v.y); d[2] = f2tf(v.z); d[3] = f2tf(v.w);
        }
        __syncthreads();

        #pragma unroll
        for (int ks = 0; ks < 4; ks++) {
            int k0 = ks * 8;
            uint32_t a[4][4], bf[4][2];
            #pragma unroll
            for (int mt = 0; mt < 4; mt++) {
                int r0 = wm * 64 + mt * 16 + (lane >> 2);
                int kc = k0 + (lane & 3);
                a[mt][0] = __float_as_uint(As[r0 * 36 + kc]);
                a[mt][1] = __float_as_uint(As[(r0 + 8) * 36 + kc]);
                a[mt][2] = __float_as_uint(As[r0 * 36 + kc + 4]);
                a[mt][3] = __float_as_uint(As[(r0 + 8) * 36 + kc + 4]);
            }
            #pragma unroll
            for (int nt = 0; nt < 4; nt++) {
                int col = wn * 32 + nt * 8 + (lane >> 2);
                bf[nt][0] = __float_as_uint(Bs[(k0 + (lane & 3)) * 136 + col]);
                bf[nt][1] = __float_as_uint(Bs[(k0 + (lane & 3) + 4) * 136 + col]);
            }
            #pragma unroll
            for (int mt = 0; mt < 4; mt++)
                #pragma unroll
                for (int nt = 0; nt < 4; nt++) {
                    asm volatile(
                        "mma.sync.aligned.m16n8k8.row.col.f32.tf32.tf32.f32 "
                        "{%0,%1,%2,%3}, {%4,%5,%6,%7}, {%8,%9}, {%0,%1,%2,%3};"
                        : "+f"(c[mt][nt][0]), "+f"(c[mt][nt][1]),
                          "+f"(c[mt][nt][2]), "+f"(c[mt][nt][3])
                        : "r"(a[mt][0]), "r"(a[mt][1]), "r"(a[mt][2]), "r"(a[mt][3]),
                          "r"(bf[nt][0]), "r"(bf[nt][1]));
                }
        }
        __syncthreads();
    }

    // epilogue
    #pragma unroll
    for (int mt = 0; mt < 4; mt++) {
        int r0 = wm * 64 + mt * 16 + (lane >> 2);
        #pragma unroll
        for (int nt = 0; nt < 4; nt++) {
            int col0 = colBase + wn * 32 + nt * 8 + 2 * (lane & 3);
            #pragma unroll
            for (int half = 0; half < 2; half++) {
                size_t row = rowBase + r0 + half * 8;
                #pragma unroll
                for (int j = 0; j < 2; j++) {
                    int col = col0 + j;
                    float v = c[mt][nt][half * 2 + j] + bias[col];
                    if (EPI == 1) v += res[row * M + col];
                    if (EPI == 2) v = 0.5f * v * (1.f + erff(v * 0.70710678118f));
                    out[row * M + col] = v;
                }
            }
        }
    }
}

// ---------------- window attention: one block per (window, head) ------------
// 512 windows * 16 heads = 8192 blocks, 64 threads (one query row each)
__global__ __launch_bounds__(64)
void attn_kernel(const float* __restrict__ qkv, float* __restrict__ out) {
    int blk  = blockIdx.x;
    int head = blk & (NHEADS - 1);
    int win  = blk >> 4;
    int b  = win >> 6;
    int wi = (win >> 3) & 7;
    int wj = win & 7;
    int p = threadIdx.x;            // position in window 0..63
    int r = p >> 3, cc = p & 7;
    int t = b * (HH * WW) + (wi * 8 + r) * WW + wj * 8 + cc;

    __shared__ float Ks[64][33];    // pad to 33: conflict-free STS
    __shared__ float Vs[64][33];

    const float4* base = (const float4*)(qkv + (size_t)t * (3 * CC) + head * 96);
    float q[HD];
    #pragma unroll
    for (int i = 0; i < 8; i++) {
        float4 vq = base[i];
        q[4*i+0] = vq.x; q[4*i+1] = vq.y; q[4*i+2] = vq.z; q[4*i+3] = vq.w;
        float4 vk = base[8 + i];
        Ks[p][4*i+0] = vk.x; Ks[p][4*i+1] = vk.y; Ks[p][4*i+2] = vk.z; Ks[p][4*i+3] = vk.w;
        float4 vv = base[16 + i];
        Vs[p][4*i+0] = vv.x; Vs[p][4*i+1] = vv.y; Vs[p][4*i+2] = vv.z; Vs[p][4*i+3] = vv.w;
    }
    __syncthreads();

    const float scale = 0.17677669529663688f;  // 32^-0.5
    float s[64];
    float mx = -1e30f;
    #pragma unroll 4
    for (int j = 0; j < 64; j++) {
        float acc = 0.f;
        #pragma unroll
        for (int d = 0; d < HD; d++) acc += q[d] * Ks[j][d];
        acc *= scale;
        s[j] = acc;
        mx = fmaxf(mx, acc);
    }
    float sum = 0.f;
    #pragma unroll 4
    for (int j = 0; j < 64; j++) {
        float e = __expf(s[j] - mx);
        s[j] = e;
        sum += e;
    }
    float inv = 1.f / sum;

    float o[HD];
    #pragma unroll
    for (int d = 0; d < HD; d++) o[d] = 0.f;
    #pragma unroll 4
    for (int j = 0; j < 64; j++) {
        float pj = s[j] * inv;
        #pragma unroll
        for (int d = 0; d < HD; d++) o[d] += pj * Vs[j][d];
    }

    float4* op = (float4*)(out + (size_t)t * CC + head * HD);
    #pragma unroll
    for (int i = 0; i < 8; i++) {
        float4 v; v.x = o[4*i]; v.y = o[4*i+1]; v.z = o[4*i+2]; v.w = o[4*i+3];
        op[i] = v;
    }
}

// ---------------- launch -----------------------------------------------------
extern "C" void kernel_launch(void* const* d_in, const int* in_sizes, int n_in,
                              void* d_out, int out_size) {
    const float* x      = (const float*)d_in[0];
    const float* ln1_g  = (const float*)d_in[1];
    const float* ln1_b  = (const float*)d_in[2];
    const float* w_qkv  = (const float*)d_in[3];
    const float* b_qkv  = (const float*)d_in[4];
    const float* w_proj = (const float*)d_in[5];
    const float* b_proj = (const float*)d_in[6];
    const float* ln2_g  = (const float*)d_in[7];
    const float* ln2_b  = (const float*)d_in[8];
    const float* w1     = (const float*)d_in[9];
    const float* b1     = (const float*)d_in[10];
    const float* w2     = (const float*)d_in[11];
    const float* b2     = (const float*)d_in[12];
    float* out = (float*)d_out;

    float *n1, *qkv, *att, *msa, *act;
    cudaGetSymbolAddress((void**)&n1,  g_n1);
    cudaGetSymbolAddress((void**)&qkv, g_qkv);
    cudaGetSymbolAddress((void**)&att, g_att);
    cudaGetSymbolAddress((void**)&msa, g_msa);
    cudaGetSymbolAddress((void**)&act, g_act);

    // 1) LN1 (shift dropped: SHIFT==WS so rolls cancel with window partition)
    ln_kernel<<<NTOK, 256>>>(x, ln1_g, ln1_b, n1);
    // 2) qkv = n1 @ w_qkv + b_qkv           [32768 x 1536]
    gemm_tf32<0><<<dim3(1536 / 128, NTOK / 128), 256>>>(n1, w_qkv, b_qkv, nullptr, qkv, CC, 3 * CC);
    // 3) window attention (512 windows x 16 heads)
    attn_kernel<<<512 * NHEADS, 64>>>(qkv, att);
    // 4) msa = att @ w_proj + b_proj + x    [32768 x 512]
    gemm_tf32<1><<<dim3(CC / 128, NTOK / 128), 256>>>(att, w_proj, b_proj, x, msa, CC, CC);
    // 5) LN2 (reuse n1 buffer)
    ln_kernel<<<NTOK, 256>>>(msa, ln2_g, ln2_b, n1);
    // 6) act = gelu(n1 @ w1 + b1)           [32768 x 2048]
    gemm_tf32<2><<<dim3(E4D / 128, NTOK / 128), 256>>>(n1, w1, b1, nullptr, act, CC, E4D);
    // 7) out = act @ w2 + b2 + msa          [32768 x 512]
    gemm_tf32<1><<<dim3(CC / 128, NTOK / 128), 256>>>(act, w2, b2, msa, out, E4D, CC);
}

// round 3
// speedup vs baseline: 1.1506x; 1.1506x over previous
#include <cuda_runtime.h>
#include <cstdint>

#define BB 8
#define HH 64
#define WW 64
#define CC 512
#define NTOK (BB*HH*WW)        /* 32768 tokens */
#define E4D 2048
#define NHEADS 16
#define HD 32

// ---------------- GEMM tile config ------------------------------------------
// block tile: 128 rows (tokens) x 256 cols; 8 warps, warp tile 64x64
// k-chunk 32, 3-stage cp.async pipeline
#define KC 32
#define NSTG 3
#define AS_STRIDE 36           /* floats; conflict-free for frag reads */
#define BS_STRIDE 264          /* floats; 264 mod 32 == 8 -> conflict-free */
#define A_STAGE_F (128 * AS_STRIDE)            /* 4608 floats  = 18432 B */
#define B_STAGE_F (32 * BS_STRIDE)             /* 8448 floats  = 33792 B */
#define STAGE_F   (A_STAGE_F + B_STAGE_F)      /* 13056 floats = 52224 B */
#define SMEM_TOTAL (NSTG * STAGE_F * 4)        /* 156672 B */

// ---------------- scratch (device globals) ----------------------------------
__device__ float g_n1 [(size_t)NTOK * CC];
__device__ float g_qkv[(size_t)NTOK * 3 * CC];
__device__ float g_att[(size_t)NTOK * CC];
__device__ float g_msa[(size_t)NTOK * CC];
__device__ float g_act[(size_t)NTOK * E4D];

// ---------------- helpers ----------------------------------------------------
__device__ __forceinline__ uint32_t s2u(const void* p) {
    uint32_t a;
    asm("{ .reg .u64 t; cvta.to.shared.u64 t, %1; cvt.u32.u64 %0, t; }" : "=r"(a) : "l"(p));
    return a;
}
__device__ __forceinline__ void cpa16(uint32_t dst, const void* src) {
    asm volatile("cp.async.cg.shared.global [%0], [%1], 16;" :: "r"(dst), "l"(src));
}
#define CP_COMMIT() asm volatile("cp.async.commit_group;" ::: "memory")
#define CP_WAIT2()  asm volatile("cp.async.wait_group 2;" ::: "memory")

// ---------------- chunk loader (cp.async) ------------------------------------
__device__ __forceinline__ void load_chunk(uint32_t sb, int s, int ci, int tid,
                                           const float* __restrict__ A,
                                           const float* __restrict__ W,
                                           size_t rowBase, int colBase, int K, int M) {
    int kt = ci * KC;
    uint32_t abase = sb + (uint32_t)(s * STAGE_F * 4);
    uint32_t bbase = abase + A_STAGE_F * 4;
    // A tile: 128 rows x 32 floats  (1024 float4, 4 per thread)
    #pragma unroll
    for (int i = 0; i < 4; i++) {
        int u = tid + i * 256;
        int r = u >> 3, w = u & 7;
        cpa16(abase + (uint32_t)(r * (AS_STRIDE * 4) + w * 16),
              A + (rowBase + r) * (size_t)K + kt + w * 4);
    }
    // B tile: 32 k-rows x 256 cols  (2048 float4, 8 per thread)
    #pragma unroll
    for (int i = 0; i < 8; i++) {
        int u = tid + i * 256;
        int r = u >> 6, cq = u & 63;
        cpa16(bbase + (uint32_t)(r * (BS_STRIDE * 4) + cq * 16),
              W + (size_t)(kt + r) * M + colBase + cq * 4);
    }
    CP_COMMIT();
}

// ---------------- TF32 mma.sync GEMM, cp.async pipelined ---------------------
// out[N,M] = A[N,K] @ W[K,M] + epilogue. EPI: 0 bias, 1 bias+res, 2 bias+GELU
template<int EPI>
__global__ __launch_bounds__(256, 1)
void gemm_tf32(const float* __restrict__ A, const float* __restrict__ W,
               const float* __restrict__ bias, const float* __restrict__ res,
               float* __restrict__ out, int K, int M) {
    extern __shared__ __align__(16) float smem[];
    uint32_t sb = s2u(smem);
    int tid  = threadIdx.x;
    int lane = tid & 31;
    int warp = tid >> 5;
    int wm = warp & 1;               // 2 warps along rows (2*64 = 128)
    int wn = warp >> 1;              // 4 warps along cols (4*64 = 256)
    size_t rowBase = (size_t)blockIdx.y * 128;
    int    colBase = blockIdx.x * 256;
    int nchunk = K / KC;

    float c[4][8][4];
    #pragma unroll
    for (int i = 0; i < 4; i++)
        #pragma unroll
        for (int j = 0; j < 8; j++)
            #pragma unroll
            for (int k = 0; k < 4; k++) c[i][j][k] = 0.f;

    // prologue: 3 chunks in flight
    load_chunk(sb, 0, 0, tid, A, W, rowBase, colBase, K, M);
    load_chunk(sb, 1, 1, tid, A, W, rowBase, colBase, K, M);
    load_chunk(sb, 2, 2, tid, A, W, rowBase, colBase, K, M);

    for (int ci = 0; ci < nchunk; ci++) {
        int s = ci % NSTG;
        CP_WAIT2();
        __syncthreads();

        const float* As = smem + s * STAGE_F;
        const float* Bs = As + A_STAGE_F;

        #pragma unroll
        for (int ks = 0; ks < 4; ks++) {
            int k0 = ks * 8;
            uint32_t a[4][4];
            #pragma unroll
            for (int mt = 0; mt < 4; mt++) {
                int r0 = wm * 64 + mt * 16 + (lane >> 2);
                int kc = k0 + (lane & 3);
                a[mt][0] = __float_as_uint(As[r0 * AS_STRIDE + kc]);
                a[mt][1] = __float_as_uint(As[(r0 + 8) * AS_STRIDE + kc]);
                a[mt][2] = __float_as_uint(As[r0 * AS_STRIDE + kc + 4]);
                a[mt][3] = __float_as_uint(As[(r0 + 8) * AS_STRIDE + kc + 4]);
            }
            #pragma unroll
            for (int nt = 0; nt < 8; nt++) {
                int col = wn * 64 + nt * 8 + (lane >> 2);
                uint32_t b0 = __float_as_uint(Bs[(k0 + (lane & 3)) * BS_STRIDE + col]);
                uint32_t b1 = __float_as_uint(Bs[(k0 + (lane & 3) + 4) * BS_STRIDE + col]);
                #pragma unroll
                for (int mt = 0; mt < 4; mt++) {
                    asm volatile(
                        "mma.sync.aligned.m16n8k8.row.col.f32.tf32.tf32.f32 "
                        "{%0,%1,%2,%3}, {%4,%5,%6,%7}, {%8,%9}, {%0,%1,%2,%3};"
                        : "+f"(c[mt][nt][0]), "+f"(c[mt][nt][1]),
                          "+f"(c[mt][nt][2]), "+f"(c[mt][nt][3])
                        : "r"(a[mt][0]), "r"(a[mt][1]), "r"(a[mt][2]), "r"(a[mt][3]),
                          "r"(b0), "r"(b1));
                }
            }
        }
        __syncthreads();
        if (ci + 3 < nchunk)
            load_chunk(sb, s, ci + 3, tid, A, W, rowBase, colBase, K, M);
    }

    // ---------------- epilogue ----------------
    #pragma unroll
    for (int mt = 0; mt < 4; mt++) {
        int r0 = wm * 64 + mt * 16 + (lane >> 2);
        #pragma unroll
        for (int nt = 0; nt < 8; nt++) {
            int col = colBase + wn * 64 + nt * 8 + 2 * (lane & 3);
            float2 bv = *(const float2*)(bias + col);
            #pragma unroll
            for (int half = 0; half < 2; half++) {
                size_t row = rowBase + r0 + half * 8;
                float v0 = c[mt][nt][half * 2 + 0] + bv.x;
                float v1 = c[mt][nt][half * 2 + 1] + bv.y;
                if (EPI == 1) {
                    float2 rv = *(const float2*)(res + row * (size_t)M + col);
                    v0 += rv.x; v1 += rv.y;
                }
                if (EPI == 2) {
                    v0 = 0.5f * v0 * (1.f + erff(v0 * 0.70710678118f));
                    v1 = 0.5f * v1 * (1.f + erff(v1 * 0.70710678118f));
                }
                float2 ov; ov.x = v0; ov.y = v1;
                *(float2*)(out + row * (size_t)M + col) = ov;
            }
        }
    }
}

// ---------------- LayerNorm --------------------------------------------------
__global__ void ln_kernel(const float* __restrict__ in,
                          const float* __restrict__ g,
                          const float* __restrict__ b,
                          float* __restrict__ out) {
    int row = blockIdx.x;
    int tid = threadIdx.x;
    const float2* xr = (const float2*)(in + (size_t)row * CC);
    float2 v = xr[tid];
    float s  = v.x + v.y;
    float sq = v.x * v.x + v.y * v.y;
    #pragma unroll
    for (int o = 16; o; o >>= 1) {
        s  += __shfl_xor_sync(0xffffffffu, s,  o);
        sq += __shfl_xor_sync(0xffffffffu, sq, o);
    }
    __shared__ float ss[8], sqq[8];
    int w = tid >> 5, l = tid & 31;
    if (!l) { ss[w] = s; sqq[w] = sq; }
    __syncthreads();
    s = 0.f; sq = 0.f;
    #pragma unroll
    for (int i = 0; i < 8; i++) { s += ss[i]; sq += sqq[i]; }
    float mean = s * (1.f / CC);
    float var  = sq * (1.f / CC) - mean * mean;
    float rstd = rsqrtf(var + 1e-5f);
    float2 gg = ((const float2*)g)[tid];
    float2 bb = ((const float2*)b)[tid];
    float2 o;
    o.x = (v.x - mean) * rstd * gg.x + bb.x;
    o.y = (v.y - mean) * rstd * gg.y + bb.y;
    ((float2*)(out + (size_t)row * CC))[tid] = o;
}

// ---------------- window attention -------------------------------------------
__global__ __launch_bounds__(64)
void attn_kernel(const float* __restrict__ qkv, float* __restrict__ out) {
    int blk  = blockIdx.x;
    int head = blk & (NHEADS - 1);
    int win  = blk >> 4;
    int b  = win >> 6;
    int wi = (win >> 3) & 7;
    int wj = win & 7;
    int p = threadIdx.x;
    int r = p >> 3, cc = p & 7;
    int t = b * (HH * WW) + (wi * 8 + r) * WW + wj * 8 + cc;

    __shared__ float Ks[64][33];
    __shared__ float Vs[64][33];

    const float4* base = (const float4*)(qkv + (size_t)t * (3 * CC) + head * 96);
    float q[HD];
    #pragma unroll
    for (int i = 0; i < 8; i++) {
        float4 vq = base[i];
        q[4*i+0] = vq.x; q[4*i+1] = vq.y; q[4*i+2] = vq.z; q[4*i+3] = vq.w;
        float4 vk = base[8 + i];
        Ks[p][4*i+0] = vk.x; Ks[p][4*i+1] = vk.y; Ks[p][4*i+2] = vk.z; Ks[p][4*i+3] = vk.w;
        float4 vv = base[16 + i];
        Vs[p][4*i+0] = vv.x; Vs[p][4*i+1] = vv.y; Vs[p][4*i+2] = vv.z; Vs[p][4*i+3] = vv.w;
    }
    __syncthreads();

    const float scale = 0.17677669529663688f;
    float s[64];
    float mx = -1e30f;
    #pragma unroll 4
    for (int j = 0; j < 64; j++) {
        float acc = 0.f;
        #pragma unroll
        for (int d = 0; d < HD; d++) acc += q[d] * Ks[j][d];
        acc *= scale;
        s[j] = acc;
        mx = fmaxf(mx, acc);
    }
    float sum = 0.f;
    #pragma unroll 4
    for (int j = 0; j < 64; j++) {
        float e = __expf(s[j] - mx);
        s[j] = e;
        sum += e;
    }
    float inv = 1.f / sum;

    float o[HD];
    #pragma unroll
    for (int d = 0; d < HD; d++) o[d] = 0.f;
    #pragma unroll 4
    for (int j = 0; j < 64; j++) {
        float pj = s[j] * inv;
        #pragma unroll
        for (int d = 0; d < HD; d++) o[d] += pj * Vs[j][d];
    }

    float4* op = (float4*)(out + (size_t)t * CC + head * HD);
    #pragma unroll
    for (int i = 0; i < 8; i++) {
        float4 v; v.x = o[4*i]; v.y = o[4*i+1]; v.z = o[4*i+2]; v.w = o[4*i+3];
        op[i] = v;
    }
}

// ---------------- launch -----------------------------------------------------
extern "C" void kernel_launch(void* const* d_in, const int* in_sizes, int n_in,
                              void* d_out, int out_size) {
    const float* x      = (const float*)d_in[0];
    const float* ln1_g  = (const float*)d_in[1];
    const float* ln1_b  = (const float*)d_in[2];
    const float* w_qkv  = (const float*)d_in[3];
    const float* b_qkv  = (const float*)d_in[4];
    const float* w_proj = (const float*)d_in[5];
    const float* b_proj = (const float*)d_in[6];
    const float* ln2_g  = (const float*)d_in[7];
    const float* ln2_b  = (const float*)d_in[8];
    const float* w1     = (const float*)d_in[9];
    const float* b1     = (const float*)d_in[10];
    const float* w2     = (const float*)d_in[11];
    const float* b2     = (const float*)d_in[12];
    float* out = (float*)d_out;

    float *n1, *qkv, *att, *msa, *act;
    cudaGetSymbolAddress((void**)&n1,  g_n1);
    cudaGetSymbolAddress((void**)&qkv, g_qkv);
    cudaGetSymbolAddress((void**)&att, g_att);
    cudaGetSymbolAddress((void**)&msa, g_msa);
    cudaGetSymbolAddress((void**)&act, g_act);

    cudaFuncSetAttribute(gemm_tf32<0>, cudaFuncAttributeMaxDynamicSharedMemorySize, SMEM_TOTAL);
    cudaFuncSetAttribute(gemm_tf32<1>, cudaFuncAttributeMaxDynamicSharedMemorySize, SMEM_TOTAL);
    cudaFuncSetAttribute(gemm_tf32<2>, cudaFuncAttributeMaxDynamicSharedMemorySize, SMEM_TOTAL);

    // 1) LN1 (shift dropped: SHIFT==WS so rolls cancel with window partition)
    ln_kernel<<<NTOK, 256>>>(x, ln1_g, ln1_b, n1);
    // 2) qkv = n1 @ w_qkv + b_qkv           [32768 x 1536]
    gemm_tf32<0><<<dim3(1536 / 256, NTOK / 128), 256, SMEM_TOTAL>>>(n1, w_qkv, b_qkv, nullptr, qkv, CC, 3 * CC);
    // 3) window attention (512 windows x 16 heads)
    attn_kernel<<<512 * NHEADS, 64>>>(qkv, att);
    // 4) msa = att @ w_proj + b_proj + x    [32768 x 512]
    gemm_tf32<1><<<dim3(CC / 256, NTOK / 128), 256, SMEM_TOTAL>>>(att, w_proj, b_proj, x, msa, CC, CC);
    // 5) LN2 (reuse n1 buffer)
    ln_kernel<<<NTOK, 256>>>(msa, ln2_g, ln2_b, n1);
    // 6) act = gelu(n1 @ w1 + b1)           [32768 x 2048]
    gemm_tf32<2><<<dim3(E4D / 256, NTOK / 128), 256, SMEM_TOTAL>>>(n1, w1, b1, nullptr, act, CC, E4D);
    // 7) out = act @ w2 + b2 + msa          [32768 x 512]
    gemm_tf32<1><<<dim3(CC / 256, NTOK / 128), 256, SMEM_TOTAL>>>(act, w2, b2, msa, out, E4D, CC);
}